// round 13
// baseline (speedup 1.0000x reference)
#include <cuda_runtime.h>
#include <cuda_bf16.h>

// Problem constants
#define B_    2
#define H_    16
#define S_    2048
#define D_    64
#define DM    1024
#define MTOT  4096   // B_*S_

static const long OUT_ELEMS  = (long)MTOT * DM;            // 4,194,304
static const long ATTN_ELEMS = (long)B_ * H_ * S_ * S_;    // 134,217,728

// Scratch (device-global; no runtime allocation allowed)
__device__ float g_q[B_*H_*S_*D_];
__device__ float g_k[B_*H_*S_*D_];
__device__ float g_v[B_*H_*S_*D_];
__device__ float g_ctx[MTOT*DM];
__device__ float g_attn[(size_t)B_*H_*S_*S_];
__device__ float g_w[4*DM*DM];          // tf32-rounded Wq|Wk|Wv|Wo

// ---------------------------------------------------------------------------
// tf32 / mma / ldmatrix / cp.async helpers
// ---------------------------------------------------------------------------
__device__ __forceinline__ float tf(float f) {
    unsigned u;
    asm("cvt.rna.tf32.f32 %0, %1;" : "=r"(u) : "f"(f));
    return __uint_as_float(u);
}
__device__ __forceinline__ float4 tf4(float4 v) {
    float4 t; t.x = tf(v.x); t.y = tf(v.y); t.z = tf(v.z); t.w = tf(v.w); return t;
}

__device__ __forceinline__ void mma_tf32(
    float& c0, float& c1, float& c2, float& c3,
    unsigned a0, unsigned a1, unsigned a2, unsigned a3,
    unsigned b0, unsigned b1)
{
    asm volatile(
        "mma.sync.aligned.m16n8k8.row.col.f32.tf32.tf32.f32 "
        "{%0,%1,%2,%3},{%4,%5,%6,%7},{%8,%9},{%0,%1,%2,%3};"
        : "+f"(c0), "+f"(c1), "+f"(c2), "+f"(c3)
        : "r"(a0), "r"(a1), "r"(a2), "r"(a3), "r"(b0), "r"(b1));
}

__device__ __forceinline__ void ldsm4(unsigned& r0, unsigned& r1,
                                      unsigned& r2, unsigned& r3,
                                      const float* p)
{
    unsigned a = (unsigned)__cvta_generic_to_shared(p);
    asm volatile("ldmatrix.sync.aligned.m8n8.x4.shared.b16 {%0,%1,%2,%3}, [%4];"
                 : "=r"(r0), "=r"(r1), "=r"(r2), "=r"(r3) : "r"(a));
}

// 16B async copy gmem -> smem (data already tf32-rounded at the source)
__device__ __forceinline__ void cpa16(float* dst, const float* src) {
    unsigned d = (unsigned)__cvta_generic_to_shared(dst);
    asm volatile("cp.async.cg.shared.global [%0], [%1], 16;" :: "r"(d), "l"(src));
}
#define CPA_COMMIT asm volatile("cp.async.commit_group;")
#define CPA_WAIT0  asm volatile("cp.async.wait_group 0;")
#define CPA_WAIT1  asm volatile("cp.async.wait_group 1;")

// Row-major padded strides
#define ASTR 36    // gemm A tile rows (32 k + pad)
#define QSTR 68    // 64-float rows (Q/K/P) + pad
// gemm W layout (kk-interleaved, scalar LDS)
#define RSB 132
#define CSB 1056
// V tile layout: [chunk][kk][68]
#define RSV 68
#define CSV 548

// ---------------------------------------------------------------------------
// Prep: round all four weight matrices to tf32 once.  grid (1024, 4)
// ---------------------------------------------------------------------------
__global__ __launch_bounds__(256)
void tf_round_w(const float* __restrict__ Wq, const float* __restrict__ Wk,
                const float* __restrict__ Wv, const float* __restrict__ Wo,
                float* __restrict__ dst)
{
    const float* src = (blockIdx.y == 0) ? Wq : (blockIdx.y == 1) ? Wk
                     : (blockIdx.y == 2) ? Wv : Wo;
    long i = (long)blockIdx.x * 256 + threadIdx.x;
    float* d = dst + (long)blockIdx.y * DM * DM;
    ((float4*)d)[i] = tf4(((const float4*)src)[i]);
}

// ---------------------------------------------------------------------------
// Dense GEMM body: C[4096,1024] = A @ W + bias (tf32 MMA).
// 3-stage cp.async ring, wait_group 1 (one compute body of copy slack).
// ---------------------------------------------------------------------------
template<int SPLIT, int PREA>
__device__ __forceinline__
void gemm_body(const float* __restrict__ A, const float* __restrict__ W,
               const float* __restrict__ bias, float* __restrict__ C,
               float* sm, int bx, int by)
{
    float* As = sm;            // 3 bufs * 128*ASTR = 13824
    float* Bs = sm + 13824;    // 3 bufs * 4*CSB = 12672

    const int tid = threadIdx.x, lane = tid & 31, warp = tid >> 5;
    const int wm = warp >> 2, wn = warp & 3;
    const float* Ab = A + (long)by * 128 * DM;
    const float* Wb = W + (long)bx * 128;

    const int a_ch = tid & 3, a_m = tid >> 2;
    const int b_cg = tid & 31, b_k = tid >> 5;
    const int b_kk = 2 * (b_k & 3) + ((b_k >> 2) & 1);

    const int arow = (lane & 7) + ((lane >> 3) & 1) * 8;
    const int acol = ((lane >> 4) & 1) * 4;

    float acc[4][4][4];
    #pragma unroll
    for (int i = 0; i < 4; i++)
        #pragma unroll
        for (int j = 0; j < 4; j++)
            #pragma unroll
            for (int q = 0; q < 4; q++) acc[i][j][q] = 0.f;

    float4 ar[2][2];
    const int NK = DM / 32;

    // prologue: tiles 0 and 1
    #pragma unroll
    for (int t = 0; t < 2; t++) {
        float* Bd = Bs + t * 4224;
        #pragma unroll
        for (int p = 0; p < 4; p++)
            cpa16(Bd + p * CSB + b_kk * RSB + b_cg * 4,
                  Wb + (long)(t * 32 + b_k + 8 * p) * DM + b_cg * 4);
        float* Ad = As + t * 4608;
        if (PREA) {
            #pragma unroll
            for (int p = 0; p < 2; p++) {
                const float* s = Ab + (long)(a_m + 64 * p) * DM + t * 32 + a_ch * 8;
                float* d = Ad + (a_m + 64 * p) * ASTR + a_ch * 8;
                cpa16(d, s);
                cpa16(d + 4, s + 4);
            }
        } else {
            #pragma unroll
            for (int p = 0; p < 2; p++) {
                const float* s = Ab + (long)(a_m + 64 * p) * DM + t * 32 + a_ch * 8;
                ar[p][0] = *(const float4*)s;
                ar[p][1] = *(const float4*)(s + 4);
            }
            #pragma unroll
            for (int p = 0; p < 2; p++) {
                float* d = Ad + (a_m + 64 * p) * ASTR + a_ch * 8;
                *(float4*)d = tf4(ar[p][0]);
                *(float4*)(d + 4) = tf4(ar[p][1]);
            }
        }
        CPA_COMMIT;
    }
    CPA_WAIT1;          // tile 0 ready
    __syncthreads();

    for (int it = 0; it < NK; ++it) {
        const bool pre2 = (it + 2 < NK);
        if (!PREA && pre2) {
            const int k0 = (it + 2) * 32;
            #pragma unroll
            for (int p = 0; p < 2; p++) {
                const float* s = Ab + (long)(a_m + 64 * p) * DM + k0 + a_ch * 8;
                ar[p][0] = *(const float4*)s;
                ar[p][1] = *(const float4*)(s + 4);
            }
        }

        const int ib = it % 3;
        const float* Ac = As + ib * 4608;
        const float* Bc = Bs + ib * 4224;
        #pragma unroll
        for (int ch = 0; ch < 4; ch++) {
            unsigned a[4][4], b[4][2];
            #pragma unroll
            for (int mi = 0; mi < 4; mi++)
                ldsm4(a[mi][0], a[mi][1], a[mi][2], a[mi][3],
                      Ac + (wm * 64 + mi * 16 + arow) * ASTR + ch * 8 + acol);
            #pragma unroll
            for (int ni = 0; ni < 4; ni++) {
                int n = wn * 32 + ni * 8 + (lane >> 2);
                int c2 = 2 * (lane & 3);
                b[ni][0] = __float_as_uint(Bc[ch * CSB + c2 * RSB + n]);
                b[ni][1] = __float_as_uint(Bc[ch * CSB + (c2 + 1) * RSB + n]);
            }
            #pragma unroll
            for (int mi = 0; mi < 4; mi++)
                #pragma unroll
                for (int ni = 0; ni < 4; ni++)
                    mma_tf32(acc[mi][ni][0], acc[mi][ni][1], acc[mi][ni][2], acc[mi][ni][3],
                             a[mi][0], a[mi][1], a[mi][2], a[mi][3],
                             b[ni][0], b[ni][1]);
        }

        // issue tile it+2 into buffer (it+2)%3 (freed one sync ago)
        if (pre2) {
            const int k0 = (it + 2) * 32;
            const int nb = (it + 2) % 3;
            float* Bd = Bs + nb * 4224;
            #pragma unroll
            for (int p = 0; p < 4; p++)
                cpa16(Bd + p * CSB + b_kk * RSB + b_cg * 4,
                      Wb + (long)(k0 + b_k + 8 * p) * DM + b_cg * 4);
            float* Ad = As + nb * 4608;
            if (PREA) {
                #pragma unroll
                for (int p = 0; p < 2; p++) {
                    const float* s = Ab + (long)(a_m + 64 * p) * DM + k0 + a_ch * 8;
                    float* d = Ad + (a_m + 64 * p) * ASTR + a_ch * 8;
                    cpa16(d, s);
                    cpa16(d + 4, s + 4);
                }
            } else {
                #pragma unroll
                for (int p = 0; p < 2; p++) {
                    float* d = Ad + (a_m + 64 * p) * ASTR + a_ch * 8;
                    *(float4*)d = tf4(ar[p][0]);
                    *(float4*)(d + 4) = tf4(ar[p][1]);
                }
            }
        }
        CPA_COMMIT;

        if (it + 1 < NK) {
            CPA_WAIT1;      // tile it+1 ready (in-order group completion)
            __syncthreads();
        }
    }

    #pragma unroll
    for (int mi = 0; mi < 4; mi++) {
        int r0 = by * 128 + wm * 64 + mi * 16 + (lane >> 2);
        #pragma unroll
        for (int ni = 0; ni < 4; ni++) {
            int n = bx * 128 + wn * 32 + ni * 8 + 2 * (lane & 3);
            float bz0 = bias[n], bz1 = bias[n + 1];
            float2 t0, t1;
            if (SPLIT) {
                t0.x = tf(acc[mi][ni][0] + bz0); t0.y = tf(acc[mi][ni][1] + bz1);
                t1.x = tf(acc[mi][ni][2] + bz0); t1.y = tf(acc[mi][ni][3] + bz1);
                int bb = r0 >> 11, s = r0 & 2047;
                int h = n >> 6, d = n & 63;
                long base = (((long)(bb * H_ + h)) * S_ + s) * D_ + d;
                *(float2*)(C + base) = t0;
                *(float2*)(C + base + 8 * D_) = t1;
            } else {
                t0.x = acc[mi][ni][0] + bz0; t0.y = acc[mi][ni][1] + bz1;
                t1.x = acc[mi][ni][2] + bz0; t1.y = acc[mi][ni][3] + bz1;
                *(float2*)(C + (long)r0 * DM + n) = t0;
                *(float2*)(C + (long)(r0 + 8) * DM + n) = t1;
            }
        }
    }
}

__global__ __launch_bounds__(256)
void gemm_qkv(const float* __restrict__ Q, const float* __restrict__ K,
              const float* __restrict__ V, const float* __restrict__ Wt,
              const float* __restrict__ bq, const float* __restrict__ bk,
              const float* __restrict__ bv,
              float* __restrict__ qo, float* __restrict__ ko, float* __restrict__ vo)
{
    extern __shared__ float sm[];
    const int z = blockIdx.z;
    const float* A    = (z == 0) ? Q  : (z == 1) ? K  : V;
    const float* W    = Wt + (long)z * DM * DM;
    const float* bias = (z == 0) ? bq : (z == 1) ? bk : bv;
    float* C          = (z == 0) ? qo : (z == 1) ? ko : vo;
    gemm_body<1, 0>(A, W, bias, C, sm, blockIdx.x, blockIdx.y);
}

__global__ __launch_bounds__(256)
void gemm_out(const float* __restrict__ A, const float* __restrict__ W,
              const float* __restrict__ bias, float* __restrict__ C)
{
    extern __shared__ float sm[];
    gemm_body<0, 1>(A, W, bias, C, sm, blockIdx.x, blockIdx.y);
}

// ---------------------------------------------------------------------------
// Fused attention (no recompute): per CTA 128 query rows of one (b,h).
// Phase 1 (= R10 scores): sweep 2048 keys, write RAW e=exp(score+mask) with
//   evict-normal stores (keep L2-hot for phase 2), accumulate row sums in regs
//   -> invs in SMEM (no gmem round trip).
// Phase 2 (= R9 ctx, 128-row): re-read own e slab (L2-hot), normalize, write
//   final attn (__stcs streaming), stage P, accumulate ctx = P@V.
// Smem union 104960 B -> 2 CTAs/SM.
//   phase1: Qs[0,8704) Ks[8704,17408) msk[17408,19456) red[19456,19712)
//   phase2: Ps[0,17408) Vs[17408,26176) invs[26176,26240)
// ---------------------------------------------------------------------------
__global__ __launch_bounds__(256, 2)
void attn_fused(const float* __restrict__ Qh, const float* __restrict__ Kh,
                const float* __restrict__ Vh, const float* __restrict__ mask,
                float* __restrict__ attn, float* __restrict__ ctx)
{
    extern __shared__ float sm[];
    float* Qs   = sm;                   // 8704
    float* Ks   = sm + 8704;            // 2 bufs * 4352
    float* msk  = sm + 17408;           // 2048
    float* red  = sm + 19456;           // 256
    float* Ps   = sm;                   // phase2: 2 bufs * 8704
    float* Vs   = sm + 17408;           // phase2: 2 bufs * 4384
    float* invs = sm + 26176;           // 64...128

    const int tid = threadIdx.x, lane = tid & 31, warp = tid >> 5;
    const int wm = warp >> 1, wn = warp & 1;
    const int bh = blockIdx.z;
    const int row0 = blockIdx.x * 128;
    const float* Qb = Qh + ((long)bh * S_ + row0) * D_;
    const float* Kb = Kh + (long)bh * S_ * D_;
    const float* Vb = Vh + (long)bh * S_ * D_;
    float* eb = attn + (long)bh * S_ * S_ + (long)row0 * S_;
    const int bb = bh >> 4;

    #pragma unroll
    for (int i = tid; i < 512; i += 256)
        ((float4*)msk)[i] = ((const float4*)(mask + (long)bb * S_))[i];

    const int ch = tid & 7, m = tid >> 3;

    // Q (128 rows) + K tile 0 via cp.async
    #pragma unroll
    for (int p = 0; p < 4; p++) {
        int row = m + 32 * p;
        const float* sq = Qb + (long)row * D_ + ch * 8;
        float* d = Qs + row * QSTR + ch * 8;
        cpa16(d, sq);
        cpa16(d + 4, sq + 4);
    }
    #pragma unroll
    for (int p = 0; p < 2; p++) {
        int row = m + 32 * p;
        const float* sk = Kb + (long)row * D_ + ch * 8;
        float* d = Ks + row * QSTR + ch * 8;
        cpa16(d, sk);
        cpa16(d + 4, sk + 4);
    }
    CPA_COMMIT;
    CPA_WAIT0;
    __syncthreads();

    const int arow = (lane & 7) + ((lane >> 3) & 1) * 8;
    const int acol = ((lane >> 4) & 1) * 4;
    const int brow = (lane & 7) + ((lane >> 4) & 1) * 8;
    const int bcol = ((lane >> 3) & 1) * 4;

    const int r_w = wm * 32 + (lane >> 2);
    float ssum[4] = {0.f, 0.f, 0.f, 0.f};

    // ================= Phase 1: scores -> raw e + row sums =================
    const int NT = S_ / 64;   // 32
    for (int kt = 0; kt < NT; ++kt) {
        const bool pre = (kt + 1 < NT);
        if (pre) {
            const int k0 = (kt + 1) * 64;
            float* Kd = Ks + ((kt + 1) & 1) * 4352;
            #pragma unroll
            for (int p = 0; p < 2; p++) {
                int row = m + 32 * p;
                const float* sk = Kb + (long)(k0 + row) * D_ + ch * 8;
                float* d = Kd + row * QSTR + ch * 8;
                cpa16(d, sk);
                cpa16(d + 4, sk + 4);
            }
            CPA_COMMIT;
        }

        float acc[2][4][4];
        #pragma unroll
        for (int i = 0; i < 2; i++)
            #pragma unroll
            for (int j = 0; j < 4; j++)
                #pragma unroll
                for (int q = 0; q < 4; q++) acc[i][j][q] = 0.f;

        const float* Kc = Ks + (kt & 1) * 4352;
        #pragma unroll
        for (int c = 0; c < 8; c++) {
            unsigned a[2][4], b[4][2];
            #pragma unroll
            for (int mi = 0; mi < 2; mi++)
                ldsm4(a[mi][0], a[mi][1], a[mi][2], a[mi][3],
                      Qs + (wm * 32 + mi * 16 + arow) * QSTR + c * 8 + acol);
            #pragma unroll
            for (int pr = 0; pr < 2; pr++)
                ldsm4(b[2*pr][0], b[2*pr][1], b[2*pr+1][0], b[2*pr+1][1],
                      Kc + (wn * 32 + pr * 16 + brow) * QSTR + c * 8 + bcol);
            #pragma unroll
            for (int mi = 0; mi < 2; mi++)
                #pragma unroll
                for (int ni = 0; ni < 4; ni++)
                    mma_tf32(acc[mi][ni][0], acc[mi][ni][1], acc[mi][ni][2], acc[mi][ni][3],
                             a[mi][0], a[mi][1], a[mi][2], a[mi][3],
                             b[ni][0], b[ni][1]);
        }

        #pragma unroll
        for (int mi = 0; mi < 2; mi++) {
            int r = r_w + mi * 16;
            #pragma unroll
            for (int ni = 0; ni < 4; ni++) {
                int n = kt * 64 + wn * 32 + ni * 8 + 2 * (lane & 3);
                float2 mm = *(const float2*)(msk + n);
                float e0 = __expf(fmaf(acc[mi][ni][0], 0.125f, -1e9f * mm.x));
                float e1 = __expf(fmaf(acc[mi][ni][1], 0.125f, -1e9f * mm.y));
                float e2 = __expf(fmaf(acc[mi][ni][2], 0.125f, -1e9f * mm.x));
                float e3 = __expf(fmaf(acc[mi][ni][3], 0.125f, -1e9f * mm.y));
                float2 t0; t0.x = e0; t0.y = e1;
                float2 t1; t1.x = e2; t1.y = e3;
                // evict-normal: keep in L2 for phase 2 re-read
                *(float2*)(eb + (long)r * S_ + n) = t0;
                *(float2*)(eb + (long)(r + 8) * S_ + n) = t1;
                ssum[mi*2]   += e0 + e1;
                ssum[mi*2+1] += e2 + e3;
            }
        }

        if (pre) {
            CPA_WAIT0;
            __syncthreads();
        }
    }

    // row sums -> invs (SMEM only)
    #pragma unroll
    for (int i = 0; i < 4; i++) {
        ssum[i] += __shfl_xor_sync(0xFFFFFFFFu, ssum[i], 1);
        ssum[i] += __shfl_xor_sync(0xFFFFFFFFu, ssum[i], 2);
    }
    __syncthreads();   // phase-1 smem reads complete before reuse
    if ((lane & 3) == 0) {
        #pragma unroll
        for (int mi = 0; mi < 2; mi++)
            #pragma unroll
            for (int h = 0; h < 2; h++)
                red[wn * 128 + r_w + mi * 16 + 8 * h] = ssum[mi * 2 + h];
    }
    __syncthreads();
    if (tid < 128)
        invs[tid] = 1.0f / (red[tid] + red[128 + tid]);
    __syncthreads();

    // ================= Phase 2: normalize + attn write + P@V ===============
    const int c16 = tid & 15, rl = tid >> 4;
    const int vcg = tid & 15, vk = tid >> 4;

    float4 rr[8];

    // prologue: V tile 0 via cp.async; e tile 0 via registers (L2-hot)
    #pragma unroll
    for (int p = 0; p < 4; p++) {
        int key = vk + 16 * p;
        int chv = key >> 3, kk = 2 * (key & 3) + ((key >> 2) & 1);
        cpa16(Vs + chv * CSV + kk * RSV + vcg * 4, Vb + (long)key * D_ + vcg * 4);
    }
    CPA_COMMIT;
    #pragma unroll
    for (int p = 0; p < 8; p++)
        rr[p] = *(const float4*)(eb + (long)(rl + 16 * p) * S_ + c16 * 4);

    {
        #pragma unroll
        for (int p = 0; p < 8; p++) {
            int row = rl + 16 * p;
            float iv = invs[row];
            float4 e;
            e.x = rr[p].x * iv; e.y = rr[p].y * iv;
            e.z = rr[p].z * iv; e.w = rr[p].w * iv;
            __stcs((float4*)(eb + (long)row * S_ + c16 * 4), e);
            *(float4*)(Ps + row * QSTR + c16 * 4) = tf4(e);
        }
    }
    CPA_WAIT0;
    __syncthreads();

    float acco[2][4][4];
    #pragma unroll
    for (int i = 0; i < 2; i++)
        #pragma unroll
        for (int j = 0; j < 4; j++)
            #pragma unroll
            for (int q = 0; q < 4; q++) acco[i][j][q] = 0.f;

    for (int kt = 0; kt < NT; ++kt) {
        const bool pre = (kt + 1 < NT);
        if (pre) {
            const int k0 = (kt + 1) * 64;
            float* Vd = Vs + ((kt + 1) & 1) * 4384;
            #pragma unroll
            for (int p = 0; p < 4; p++) {
                int key = vk + 16 * p;
                int chv = key >> 3, kk = 2 * (key & 3) + ((key >> 2) & 1);
                cpa16(Vd + chv * CSV + kk * RSV + vcg * 4,
                      Vb + (long)(k0 + key) * D_ + vcg * 4);
            }
            CPA_COMMIT;
            #pragma unroll
            for (int p = 0; p < 8; p++)
                rr[p] = *(const float4*)(eb + (long)(rl + 16 * p) * S_ + k0 + c16 * 4);
        }

        const float* Pc = Ps + (kt & 1) * 8704;
        const float* Vc = Vs + (kt & 1) * 4384;
        #pragma unroll
        for (int c = 0; c < 8; c++) {
            unsigned a[2][4], b[4][2];
            #pragma unroll
            for (int mi = 0; mi < 2; mi++)
                ldsm4(a[mi][0], a[mi][1], a[mi][2], a[mi][3],
                      Pc + (wm * 32 + mi * 16 + arow) * QSTR + c * 8 + acol);
            #pragma unroll
            for (int ni = 0; ni < 4; ni++) {
                int n = wn * 32 + ni * 8 + (lane >> 2);
                int c2 = 2 * (lane & 3);
                b[ni][0] = __float_as_uint(Vc[c * CSV + c2 * RSV + n]);
                b[ni][1] = __float_as_uint(Vc[c * CSV + (c2 + 1) * RSV + n]);
            }
            #pragma unroll
            for (int mi = 0; mi < 2; mi++)
                #pragma unroll
                for (int ni = 0; ni < 4; ni++)
                    mma_tf32(acco[mi][ni][0], acco[mi][ni][1], acco[mi][ni][2], acco[mi][ni][3],
                             a[mi][0], a[mi][1], a[mi][2], a[mi][3],
                             b[ni][0], b[ni][1]);
        }

        if (pre) {
            const int k0 = (kt + 1) * 64;
            float* Pd = Ps + ((kt + 1) & 1) * 8704;
            #pragma unroll
            for (int p = 0; p < 8; p++) {
                int row = rl + 16 * p;
                float iv = invs[row];
                float4 e;
                e.x = rr[p].x * iv; e.y = rr[p].y * iv;
                e.z = rr[p].z * iv; e.w = rr[p].w * iv;
                __stcs((float4*)(eb + (long)row * S_ + k0 + c16 * 4), e);
                *(float4*)(Pd + row * QSTR + c16 * 4) = tf4(e);
            }
            CPA_WAIT0;
            __syncthreads();
        }
    }

    // epilogue: merged-heads ctx write (pre-rounded for gemm_out's cp.async)
    const int h = bh & 15;
    #pragma unroll
    for (int mi = 0; mi < 2; mi++) {
        int s = row0 + wm * 32 + mi * 16 + (lane >> 2);
        #pragma unroll
        for (int ni = 0; ni < 4; ni++) {
            int d = wn * 32 + ni * 8 + 2 * (lane & 3);
            long base = ((long)bb * S_ + s) * DM + h * 64 + d;
            float2 t0, t1;
            t0.x = tf(acco[mi][ni][0]); t0.y = tf(acco[mi][ni][1]);
            t1.x = tf(acco[mi][ni][2]); t1.y = tf(acco[mi][ni][3]);
            *(float2*)(ctx + base) = t0;
            *(float2*)(ctx + base + 8 * DM) = t1;
        }
    }
}

// ---------------------------------------------------------------------------
extern "C" void kernel_launch(void* const* d_in, const int* in_sizes, int n_in,
                              void* d_out, int out_size) {
    const float* Q    = (const float*)d_in[0];
    const float* K    = (const float*)d_in[1];
    const float* V    = (const float*)d_in[2];
    const float* mask = (const float*)d_in[3];
    const float* Wq   = (const float*)d_in[4];
    const float* bq   = (const float*)d_in[5];
    const float* Wk   = (const float*)d_in[6];
    const float* bk   = (const float*)d_in[7];
    const float* Wv   = (const float*)d_in[8];
    const float* bv   = (const float*)d_in[9];
    const float* Wo   = (const float*)d_in[10];
    const float* bo   = (const float*)d_in[11];
    float* out = (float*)d_out;

    float *qp, *kp, *vp, *cp, *ap, *wp;
    cudaGetSymbolAddress((void**)&qp, g_q);
    cudaGetSymbolAddress((void**)&kp, g_k);
    cudaGetSymbolAddress((void**)&vp, g_v);
    cudaGetSymbolAddress((void**)&cp, g_ctx);
    cudaGetSymbolAddress((void**)&ap, g_attn);
    cudaGetSymbolAddress((void**)&wp, g_w);

    float* attn = ((long)out_size >= OUT_ELEMS + ATTN_ELEMS) ? (out + OUT_ELEMS) : ap;

    const int SM_GEMM = (13824 + 12672) * 4;      // 105984
    const int SM_ATT  = 26304 * 4;                // 105216
    cudaFuncSetAttribute(gemm_qkv, cudaFuncAttributeMaxDynamicSharedMemorySize, SM_GEMM);
    cudaFuncSetAttribute(gemm_out, cudaFuncAttributeMaxDynamicSharedMemorySize, SM_GEMM);
    cudaFuncSetAttribute(attn_fused, cudaFuncAttributeMaxDynamicSharedMemorySize, SM_ATT);

    dim3 gw(DM * DM / 4 / 256, 4);
    tf_round_w<<<gw, 256>>>(Wq, Wk, Wv, Wo, wp);

    dim3 gq(DM / 128, MTOT / 128, 3);
    gemm_qkv<<<gq, 256, SM_GEMM>>>(Q, K, V, wp, bq, bk, bv, qp, kp, vp);

    dim3 g2(S_ / 128, 1, B_ * H_);
    attn_fused<<<g2, 256, SM_ATT>>>(qp, kp, vp, mask, attn, cp);

    dim3 g1(DM / 128, MTOT / 128);
    gemm_out<<<g1, 256, SM_GEMM>>>(cp, wp + 3 * (long)DM * DM, bo, out);
}

// round 14
// speedup vs baseline: 1.0567x; 1.0567x over previous
#include <cuda_runtime.h>
#include <cuda_bf16.h>
#include <cuda_fp16.h>

// Problem constants
#define B_    2
#define H_    16
#define S_    2048
#define D_    64
#define DM    1024
#define MTOT  4096   // B_*S_

static const long OUT_ELEMS  = (long)MTOT * DM;            // 4,194,304
static const long ATTN_ELEMS = (long)B_ * H_ * S_ * S_;    // 134,217,728

// Scratch (device-global; no runtime allocation allowed)
__device__ float  g_q[B_*H_*S_*D_];
__device__ float  g_k[B_*H_*S_*D_];
__device__ float  g_v[B_*H_*S_*D_];
__device__ float  g_ctx[MTOT*DM];
__device__ float  g_attn[(size_t)B_*H_*S_*S_];
__device__ __half g_eraw[(size_t)B_*H_*S_*S_];   // raw e = exp(score+mask), fp16
__device__ float  g_inv[B_*H_*S_];               // per-row 1/sum(exp)
__device__ float  g_w[4*DM*DM];                  // tf32-rounded Wq|Wk|Wv|Wo

// ---------------------------------------------------------------------------
// tf32 / mma / ldmatrix / cp.async helpers
// ---------------------------------------------------------------------------
__device__ __forceinline__ float tf(float f) {
    unsigned u;
    asm("cvt.rna.tf32.f32 %0, %1;" : "=r"(u) : "f"(f));
    return __uint_as_float(u);
}
__device__ __forceinline__ float4 tf4(float4 v) {
    float4 t; t.x = tf(v.x); t.y = tf(v.y); t.z = tf(v.z); t.w = tf(v.w); return t;
}

__device__ __forceinline__ void mma_tf32(
    float& c0, float& c1, float& c2, float& c3,
    unsigned a0, unsigned a1, unsigned a2, unsigned a3,
    unsigned b0, unsigned b1)
{
    asm volatile(
        "mma.sync.aligned.m16n8k8.row.col.f32.tf32.tf32.f32 "
        "{%0,%1,%2,%3},{%4,%5,%6,%7},{%8,%9},{%0,%1,%2,%3};"
        : "+f"(c0), "+f"(c1), "+f"(c2), "+f"(c3)
        : "r"(a0), "r"(a1), "r"(a2), "r"(a3), "r"(b0), "r"(b1));
}

__device__ __forceinline__ void ldsm4(unsigned& r0, unsigned& r1,
                                      unsigned& r2, unsigned& r3,
                                      const float* p)
{
    unsigned a = (unsigned)__cvta_generic_to_shared(p);
    asm volatile("ldmatrix.sync.aligned.m8n8.x4.shared.b16 {%0,%1,%2,%3}, [%4];"
                 : "=r"(r0), "=r"(r1), "=r"(r2), "=r"(r3) : "r"(a));
}

// 16B async copy gmem -> smem (data already tf32-rounded at the source)
__device__ __forceinline__ void cpa16(float* dst, const float* src) {
    unsigned d = (unsigned)__cvta_generic_to_shared(dst);
    asm volatile("cp.async.cg.shared.global [%0], [%1], 16;" :: "r"(d), "l"(src));
}
#define CPA_COMMIT asm volatile("cp.async.commit_group;")
#define CPA_WAIT0  asm volatile("cp.async.wait_group 0;")
#define CPA_WAIT1  asm volatile("cp.async.wait_group 1;")

// pack two floats to half2 bits
__device__ __forceinline__ unsigned pkh2(float a, float b) {
    __half2 h = __floats2half2_rn(a, b);
    return *reinterpret_cast<unsigned*>(&h);
}

// Row-major padded strides
#define ASTR 36    // gemm A tile rows (32 k + pad)
#define QSTR 68    // 64-float rows (Q/K/P) + pad
// gemm W layout (kk-interleaved, scalar LDS)
#define RSB 132
#define CSB 1056
// V tile layout: [chunk][kk][68]
#define RSV 68
#define CSV 548

// ---------------------------------------------------------------------------
// Prep: round all four weight matrices to tf32 once.  grid (1024, 4)
// ---------------------------------------------------------------------------
__global__ __launch_bounds__(256)
void tf_round_w(const float* __restrict__ Wq, const float* __restrict__ Wk,
                const float* __restrict__ Wv, const float* __restrict__ Wo,
                float* __restrict__ dst)
{
    const float* src = (blockIdx.y == 0) ? Wq : (blockIdx.y == 1) ? Wk
                     : (blockIdx.y == 2) ? Wv : Wo;
    long i = (long)blockIdx.x * 256 + threadIdx.x;
    float* d = dst + (long)blockIdx.y * DM * DM;
    ((float4*)d)[i] = tf4(((const float4*)src)[i]);
}

// ---------------------------------------------------------------------------
// Dense GEMM body: 3-stage cp.async ring, wait_group 1. (R12 winner.)
// ---------------------------------------------------------------------------
template<int SPLIT, int PREA>
__device__ __forceinline__
void gemm_body(const float* __restrict__ A, const float* __restrict__ W,
               const float* __restrict__ bias, float* __restrict__ C,
               float* sm, int bx, int by)
{
    float* As = sm;            // 3 bufs * 128*ASTR = 13824
    float* Bs = sm + 13824;    // 3 bufs * 4*CSB = 12672

    const int tid = threadIdx.x, lane = tid & 31, warp = tid >> 5;
    const int wm = warp >> 2, wn = warp & 3;
    const float* Ab = A + (long)by * 128 * DM;
    const float* Wb = W + (long)bx * 128;

    const int a_ch = tid & 3, a_m = tid >> 2;
    const int b_cg = tid & 31, b_k = tid >> 5;
    const int b_kk = 2 * (b_k & 3) + ((b_k >> 2) & 1);

    const int arow = (lane & 7) + ((lane >> 3) & 1) * 8;
    const int acol = ((lane >> 4) & 1) * 4;

    float acc[4][4][4];
    #pragma unroll
    for (int i = 0; i < 4; i++)
        #pragma unroll
        for (int j = 0; j < 4; j++)
            #pragma unroll
            for (int q = 0; q < 4; q++) acc[i][j][q] = 0.f;

    float4 ar[2][2];
    const int NK = DM / 32;

    #pragma unroll
    for (int t = 0; t < 2; t++) {
        float* Bd = Bs + t * 4224;
        #pragma unroll
        for (int p = 0; p < 4; p++)
            cpa16(Bd + p * CSB + b_kk * RSB + b_cg * 4,
                  Wb + (long)(t * 32 + b_k + 8 * p) * DM + b_cg * 4);
        float* Ad = As + t * 4608;
        if (PREA) {
            #pragma unroll
            for (int p = 0; p < 2; p++) {
                const float* s = Ab + (long)(a_m + 64 * p) * DM + t * 32 + a_ch * 8;
                float* d = Ad + (a_m + 64 * p) * ASTR + a_ch * 8;
                cpa16(d, s);
                cpa16(d + 4, s + 4);
            }
        } else {
            #pragma unroll
            for (int p = 0; p < 2; p++) {
                const float* s = Ab + (long)(a_m + 64 * p) * DM + t * 32 + a_ch * 8;
                ar[p][0] = *(const float4*)s;
                ar[p][1] = *(const float4*)(s + 4);
            }
            #pragma unroll
            for (int p = 0; p < 2; p++) {
                float* d = Ad + (a_m + 64 * p) * ASTR + a_ch * 8;
                *(float4*)d = tf4(ar[p][0]);
                *(float4*)(d + 4) = tf4(ar[p][1]);
            }
        }
        CPA_COMMIT;
    }
    CPA_WAIT1;
    __syncthreads();

    for (int it = 0; it < NK; ++it) {
        const bool pre2 = (it + 2 < NK);
        if (!PREA && pre2) {
            const int k0 = (it + 2) * 32;
            #pragma unroll
            for (int p = 0; p < 2; p++) {
                const float* s = Ab + (long)(a_m + 64 * p) * DM + k0 + a_ch * 8;
                ar[p][0] = *(const float4*)s;
                ar[p][1] = *(const float4*)(s + 4);
            }
        }

        const int ib = it % 3;
        const float* Ac = As + ib * 4608;
        const float* Bc = Bs + ib * 4224;
        #pragma unroll
        for (int ch = 0; ch < 4; ch++) {
            unsigned a[4][4], b[4][2];
            #pragma unroll
            for (int mi = 0; mi < 4; mi++)
                ldsm4(a[mi][0], a[mi][1], a[mi][2], a[mi][3],
                      Ac + (wm * 64 + mi * 16 + arow) * ASTR + ch * 8 + acol);
            #pragma unroll
            for (int ni = 0; ni < 4; ni++) {
                int n = wn * 32 + ni * 8 + (lane >> 2);
                int c2 = 2 * (lane & 3);
                b[ni][0] = __float_as_uint(Bc[ch * CSB + c2 * RSB + n]);
                b[ni][1] = __float_as_uint(Bc[ch * CSB + (c2 + 1) * RSB + n]);
            }
            #pragma unroll
            for (int mi = 0; mi < 4; mi++)
                #pragma unroll
                for (int ni = 0; ni < 4; ni++)
                    mma_tf32(acc[mi][ni][0], acc[mi][ni][1], acc[mi][ni][2], acc[mi][ni][3],
                             a[mi][0], a[mi][1], a[mi][2], a[mi][3],
                             b[ni][0], b[ni][1]);
        }

        if (pre2) {
            const int k0 = (it + 2) * 32;
            const int nb = (it + 2) % 3;
            float* Bd = Bs + nb * 4224;
            #pragma unroll
            for (int p = 0; p < 4; p++)
                cpa16(Bd + p * CSB + b_kk * RSB + b_cg * 4,
                      Wb + (long)(k0 + b_k + 8 * p) * DM + b_cg * 4);
            float* Ad = As + nb * 4608;
            if (PREA) {
                #pragma unroll
                for (int p = 0; p < 2; p++) {
                    const float* s = Ab + (long)(a_m + 64 * p) * DM + k0 + a_ch * 8;
                    float* d = Ad + (a_m + 64 * p) * ASTR + a_ch * 8;
                    cpa16(d, s);
                    cpa16(d + 4, s + 4);
                }
            } else {
                #pragma unroll
                for (int p = 0; p < 2; p++) {
                    float* d = Ad + (a_m + 64 * p) * ASTR + a_ch * 8;
                    *(float4*)d = tf4(ar[p][0]);
                    *(float4*)(d + 4) = tf4(ar[p][1]);
                }
            }
        }
        CPA_COMMIT;

        if (it + 1 < NK) {
            CPA_WAIT1;
            __syncthreads();
        }
    }

    #pragma unroll
    for (int mi = 0; mi < 4; mi++) {
        int r0 = by * 128 + wm * 64 + mi * 16 + (lane >> 2);
        #pragma unroll
        for (int ni = 0; ni < 4; ni++) {
            int n = bx * 128 + wn * 32 + ni * 8 + 2 * (lane & 3);
            float bz0 = bias[n], bz1 = bias[n + 1];
            float2 t0, t1;
            if (SPLIT) {
                t0.x = tf(acc[mi][ni][0] + bz0); t0.y = tf(acc[mi][ni][1] + bz1);
                t1.x = tf(acc[mi][ni][2] + bz0); t1.y = tf(acc[mi][ni][3] + bz1);
                int bb = r0 >> 11, s = r0 & 2047;
                int h = n >> 6, d = n & 63;
                long base = (((long)(bb * H_ + h)) * S_ + s) * D_ + d;
                *(float2*)(C + base) = t0;
                *(float2*)(C + base + 8 * D_) = t1;
            } else {
                t0.x = acc[mi][ni][0] + bz0; t0.y = acc[mi][ni][1] + bz1;
                t1.x = acc[mi][ni][2] + bz0; t1.y = acc[mi][ni][3] + bz1;
                *(float2*)(C + (long)r0 * DM + n) = t0;
                *(float2*)(C + (long)(r0 + 8) * DM + n) = t1;
            }
        }
    }
}

__global__ __launch_bounds__(256)
void gemm_qkv(const float* __restrict__ Q, const float* __restrict__ K,
              const float* __restrict__ V, const float* __restrict__ Wt,
              const float* __restrict__ bq, const float* __restrict__ bk,
              const float* __restrict__ bv,
              float* __restrict__ qo, float* __restrict__ ko, float* __restrict__ vo)
{
    extern __shared__ float sm[];
    const int z = blockIdx.z;
    const float* A    = (z == 0) ? Q  : (z == 1) ? K  : V;
    const float* W    = Wt + (long)z * DM * DM;
    const float* bias = (z == 0) ? bq : (z == 1) ? bk : bv;
    float* C          = (z == 0) ? qo : (z == 1) ? ko : vo;
    gemm_body<1, 0>(A, W, bias, C, sm, blockIdx.x, blockIdx.y);
}

__global__ __launch_bounds__(256)
void gemm_out(const float* __restrict__ A, const float* __restrict__ W,
              const float* __restrict__ bias, float* __restrict__ C)
{
    extern __shared__ float sm[];
    gemm_body<0, 1>(A, W, bias, C, sm, blockIdx.x, blockIdx.y);
}

// ---------------------------------------------------------------------------
// K2: scores -> raw e (fp16) + row sums. 128-row CTA, 8 warps 4m x 2n,
// 2 CTAs/SM. (R12 winner loop; stores halved to fp16.)
// ---------------------------------------------------------------------------
__global__ __launch_bounds__(256, 2)
void scores_exp_tc(const float* __restrict__ Qh, const float* __restrict__ Kh,
                   const float* __restrict__ mask,
                   __half* __restrict__ eraw, float* __restrict__ inv_out)
{
    extern __shared__ float sm[];
    float* Qs  = sm;                    // 128*QSTR = 8704
    float* Ks  = sm + 8704;             // 2 bufs * 64*QSTR = 8704
    float* msk = sm + 8704 + 8704;      // 2048
    float* red = msk + 2048;            // 256

    const int tid = threadIdx.x, lane = tid & 31, warp = tid >> 5;
    const int wm = warp >> 1, wn = warp & 1;
    const int bh = blockIdx.z;
    const int row0 = blockIdx.x * 128;
    const float* Qb = Qh + ((long)bh * S_ + row0) * D_;
    const float* Kb = Kh + (long)bh * S_ * D_;
    __half* eb = eraw + (long)bh * S_ * S_ + (long)row0 * S_;
    const int bb = bh >> 4;

    #pragma unroll
    for (int i = tid; i < 512; i += 256)
        ((float4*)msk)[i] = ((const float4*)(mask + (long)bb * S_))[i];

    const int ch = tid & 7, m = tid >> 3;

    #pragma unroll
    for (int p = 0; p < 4; p++) {
        int row = m + 32 * p;
        const float* sq = Qb + (long)row * D_ + ch * 8;
        float* d = Qs + row * QSTR + ch * 8;
        cpa16(d, sq);
        cpa16(d + 4, sq + 4);
    }
    #pragma unroll
    for (int p = 0; p < 2; p++) {
        int row = m + 32 * p;
        const float* sk = Kb + (long)row * D_ + ch * 8;
        float* d = Ks + row * QSTR + ch * 8;
        cpa16(d, sk);
        cpa16(d + 4, sk + 4);
    }
    CPA_COMMIT;
    CPA_WAIT0;
    __syncthreads();

    const int arow = (lane & 7) + ((lane >> 3) & 1) * 8;
    const int acol = ((lane >> 4) & 1) * 4;
    const int brow = (lane & 7) + ((lane >> 4) & 1) * 8;
    const int bcol = ((lane >> 3) & 1) * 4;

    const int r_w = wm * 32 + (lane >> 2);
    float ssum[4] = {0.f, 0.f, 0.f, 0.f};

    const int NT = S_ / 64;   // 32
    for (int kt = 0; kt < NT; ++kt) {
        const bool pre = (kt + 1 < NT);
        if (pre) {
            const int k0 = (kt + 1) * 64;
            float* Kd = Ks + ((kt + 1) & 1) * 4352;
            #pragma unroll
            for (int p = 0; p < 2; p++) {
                int row = m + 32 * p;
                const float* sk = Kb + (long)(k0 + row) * D_ + ch * 8;
                float* d = Kd + row * QSTR + ch * 8;
                cpa16(d, sk);
                cpa16(d + 4, sk + 4);
            }
            CPA_COMMIT;
        }

        float acc[2][4][4];
        #pragma unroll
        for (int i = 0; i < 2; i++)
            #pragma unroll
            for (int j = 0; j < 4; j++)
                #pragma unroll
                for (int q = 0; q < 4; q++) acc[i][j][q] = 0.f;

        const float* Kc = Ks + (kt & 1) * 4352;
        #pragma unroll
        for (int c = 0; c < 8; c++) {
            unsigned a[2][4], b[4][2];
            #pragma unroll
            for (int mi = 0; mi < 2; mi++)
                ldsm4(a[mi][0], a[mi][1], a[mi][2], a[mi][3],
                      Qs + (wm * 32 + mi * 16 + arow) * QSTR + c * 8 + acol);
            #pragma unroll
            for (int pr = 0; pr < 2; pr++)
                ldsm4(b[2*pr][0], b[2*pr][1], b[2*pr+1][0], b[2*pr+1][1],
                      Kc + (wn * 32 + pr * 16 + brow) * QSTR + c * 8 + bcol);
            #pragma unroll
            for (int mi = 0; mi < 2; mi++)
                #pragma unroll
                for (int ni = 0; ni < 4; ni++)
                    mma_tf32(acc[mi][ni][0], acc[mi][ni][1], acc[mi][ni][2], acc[mi][ni][3],
                             a[mi][0], a[mi][1], a[mi][2], a[mi][3],
                             b[ni][0], b[ni][1]);
        }

        #pragma unroll
        for (int mi = 0; mi < 2; mi++) {
            int r = r_w + mi * 16;
            #pragma unroll
            for (int ni = 0; ni < 4; ni++) {
                int n = kt * 64 + wn * 32 + ni * 8 + 2 * (lane & 3);
                float2 mm = *(const float2*)(msk + n);
                float e0 = __expf(fmaf(acc[mi][ni][0], 0.125f, -1e9f * mm.x));
                float e1 = __expf(fmaf(acc[mi][ni][1], 0.125f, -1e9f * mm.y));
                float e2 = __expf(fmaf(acc[mi][ni][2], 0.125f, -1e9f * mm.x));
                float e3 = __expf(fmaf(acc[mi][ni][3], 0.125f, -1e9f * mm.y));
                __stcs((unsigned*)(eb + (long)r * S_ + n), pkh2(e0, e1));
                __stcs((unsigned*)(eb + (long)(r + 8) * S_ + n), pkh2(e2, e3));
                ssum[mi*2]   += e0 + e1;
                ssum[mi*2+1] += e2 + e3;
            }
        }

        if (pre) {
            CPA_WAIT0;
            __syncthreads();
        }
    }

    #pragma unroll
    for (int i = 0; i < 4; i++) {
        ssum[i] += __shfl_xor_sync(0xFFFFFFFFu, ssum[i], 1);
        ssum[i] += __shfl_xor_sync(0xFFFFFFFFu, ssum[i], 2);
    }
    if ((lane & 3) == 0) {
        #pragma unroll
        for (int mi = 0; mi < 2; mi++)
            #pragma unroll
            for (int h = 0; h < 2; h++)
                red[wn * 128 + r_w + mi * 16 + 8 * h] = ssum[mi * 2 + h];
    }
    __syncthreads();
    if (tid < 128)
        inv_out[(long)bh * S_ + row0 + tid] = 1.0f / (red[tid] + red[128 + tid]);
}

// ---------------------------------------------------------------------------
// K3: read fp16 raw e, normalize -> write fp32 attn + P@V.
// 64-ROW CTAs, 3 CTAs/SM. (R10/R12 winner loop; e-reads halved to fp16.)
// ---------------------------------------------------------------------------
__global__ __launch_bounds__(256, 3)
void ctx_attn_tc(const __half* __restrict__ eraw, float* __restrict__ attn,
                 const float* __restrict__ Vh, const float* __restrict__ inv_in,
                 float* __restrict__ ctx)
{
    extern __shared__ float sm[];
    float* Ps   = sm;                 // 2 bufs * 64*QSTR = 8704
    float* Vs   = sm + 8704;          // 2 bufs * 4384 = 8768
    float* invs = sm + 17472;         // 64

    const int tid = threadIdx.x, lane = tid & 31, warp = tid >> 5;
    const int wm = warp >> 1, wn = warp & 1;
    const int bh = blockIdx.z;
    const int row0 = blockIdx.x * 64;
    const __half* rawb = eraw + (long)bh * S_ * S_ + (long)row0 * S_;
    float* attnb = attn + (long)bh * S_ * S_ + (long)row0 * S_;
    const float* Vb = Vh + (long)bh * S_ * D_;

    if (tid < 64) invs[tid] = inv_in[(long)bh * S_ + row0 + tid];
    __syncthreads();

    const int c16 = tid & 15, rl = tid >> 4;
    const int vcg = tid & 15, vk = tid >> 4;

    const int arow = (lane & 7) + ((lane >> 3) & 1) * 8;
    const int acol = ((lane >> 4) & 1) * 4;

    uint2 hr[4];

    #pragma unroll
    for (int p = 0; p < 4; p++) {
        int key = vk + 16 * p;
        int chv = key >> 3, kk = 2 * (key & 3) + ((key >> 2) & 1);
        cpa16(Vs + chv * CSV + kk * RSV + vcg * 4, Vb + (long)key * D_ + vcg * 4);
    }
    CPA_COMMIT;
    #pragma unroll
    for (int p = 0; p < 4; p++)
        hr[p] = __ldcs((const uint2*)(rawb + (long)(rl + 16 * p) * S_ + c16 * 4));

    {
        #pragma unroll
        for (int p = 0; p < 4; p++) {
            int row = rl + 16 * p;
            float iv = invs[row];
            float2 f01 = __half22float2(*reinterpret_cast<__half2*>(&hr[p].x));
            float2 f23 = __half22float2(*reinterpret_cast<__half2*>(&hr[p].y));
            float4 e;
            e.x = f01.x * iv; e.y = f01.y * iv;
            e.z = f23.x * iv; e.w = f23.y * iv;
            __stcs((float4*)(attnb + (long)row * S_ + c16 * 4), e);
            *(float4*)(Ps + row * QSTR + c16 * 4) = tf4(e);
        }
    }
    CPA_WAIT0;
    __syncthreads();

    float acc[4][4];
    #pragma unroll
    for (int j = 0; j < 4; j++)
        #pragma unroll
        for (int q = 0; q < 4; q++) acc[j][q] = 0.f;

    const int NT = S_ / 64;   // 32
    for (int kt = 0; kt < NT; ++kt) {
        const bool pre = (kt + 1 < NT);
        if (pre) {
            const int k0 = (kt + 1) * 64;
            float* Vd = Vs + ((kt + 1) & 1) * 4384;
            #pragma unroll
            for (int p = 0; p < 4; p++) {
                int key = vk + 16 * p;
                int chv = key >> 3, kk = 2 * (key & 3) + ((key >> 2) & 1);
                cpa16(Vd + chv * CSV + kk * RSV + vcg * 4,
                      Vb + (long)(k0 + key) * D_ + vcg * 4);
            }
            CPA_COMMIT;
            #pragma unroll
            for (int p = 0; p < 4; p++)
                hr[p] = __ldcs((const uint2*)(rawb + (long)(rl + 16 * p) * S_ + k0 + c16 * 4));
        }

        const float* Pc = Ps + (kt & 1) * 4352;
        const float* Vc = Vs + (kt & 1) * 4384;
        #pragma unroll
        for (int c = 0; c < 8; c++) {
            unsigned a[4], b[4][2];
            ldsm4(a[0], a[1], a[2], a[3],
                  Pc + (wm * 16 + arow) * QSTR + c * 8 + acol);
            #pragma unroll
            for (int ni = 0; ni < 4; ni++) {
                int n = wn * 32 + ni * 8 + (lane >> 2);
                int c2 = 2 * (lane & 3);
                b[ni][0] = __float_as_uint(Vc[c * CSV + c2 * RSV + n]);
                b[ni][1] = __float_as_uint(Vc[c * CSV + (c2 + 1) * RSV + n]);
            }
            #pragma unroll
            for (int ni = 0; ni < 4; ni++)
                mma_tf32(acc[ni][0], acc[ni][1], acc[ni][2], acc[ni][3],
                         a[0], a[1], a[2], a[3], b[ni][0], b[ni][1]);
        }

        if (pre) {
            const int k0 = (kt + 1) * 64;
            float* Pd = Ps + ((kt + 1) & 1) * 4352;
            #pragma unroll
            for (int p = 0; p < 4; p++) {
                int row = rl + 16 * p;
                float iv = invs[row];
                float2 f01 = __half22float2(*reinterpret_cast<__half2*>(&hr[p].x));
                float2 f23 = __half22float2(*reinterpret_cast<__half2*>(&hr[p].y));
                float4 e;
                e.x = f01.x * iv; e.y = f01.y * iv;
                e.z = f23.x * iv; e.w = f23.y * iv;
                __stcs((float4*)(attnb + (long)row * S_ + k0 + c16 * 4), e);
                *(float4*)(Pd + row * QSTR + c16 * 4) = tf4(e);
            }
            CPA_WAIT0;
            __syncthreads();
        }
    }

    const int bb = bh >> 4, h = bh & 15;
    {
        int s = row0 + wm * 16 + (lane >> 2);
        #pragma unroll
        for (int ni = 0; ni < 4; ni++) {
            int d = wn * 32 + ni * 8 + 2 * (lane & 3);
            long base = ((long)bb * S_ + s) * DM + h * 64 + d;
            float2 t0, t1;
            t0.x = tf(acc[ni][0]); t0.y = tf(acc[ni][1]);
            t1.x = tf(acc[ni][2]); t1.y = tf(acc[ni][3]);
            *(float2*)(ctx + base) = t0;
            *(float2*)(ctx + base + 8 * DM) = t1;
        }
    }
}

// ---------------------------------------------------------------------------
extern "C" void kernel_launch(void* const* d_in, const int* in_sizes, int n_in,
                              void* d_out, int out_size) {
    const float* Q    = (const float*)d_in[0];
    const float* K    = (const float*)d_in[1];
    const float* V    = (const float*)d_in[2];
    const float* mask = (const float*)d_in[3];
    const float* Wq   = (const float*)d_in[4];
    const float* bq   = (const float*)d_in[5];
    const float* Wk   = (const float*)d_in[6];
    const float* bk   = (const float*)d_in[7];
    const float* Wv   = (const float*)d_in[8];
    const float* bv   = (const float*)d_in[9];
    const float* Wo   = (const float*)d_in[10];
    const float* bo   = (const float*)d_in[11];
    float* out = (float*)d_out;

    float *qp, *kp, *vp, *cp, *ap, *ip, *wp;
    __half* ep;
    cudaGetSymbolAddress((void**)&qp, g_q);
    cudaGetSymbolAddress((void**)&kp, g_k);
    cudaGetSymbolAddress((void**)&vp, g_v);
    cudaGetSymbolAddress((void**)&cp, g_ctx);
    cudaGetSymbolAddress((void**)&ap, g_attn);
    cudaGetSymbolAddress((void**)&ep, g_eraw);
    cudaGetSymbolAddress((void**)&ip, g_inv);
    cudaGetSymbolAddress((void**)&wp, g_w);

    float* attn = ((long)out_size >= OUT_ELEMS + ATTN_ELEMS) ? (out + OUT_ELEMS) : ap;

    const int SM_GEMM = (13824 + 12672) * 4;      // 105984
    const int SM_SCR  = (8704 + 8704 + 2048 + 256) * 4;   // 78848
    const int SM_CTX  = (8704 + 8768 + 64) * 4;   // 70144
    cudaFuncSetAttribute(gemm_qkv, cudaFuncAttributeMaxDynamicSharedMemorySize, SM_GEMM);
    cudaFuncSetAttribute(gemm_out, cudaFuncAttributeMaxDynamicSharedMemorySize, SM_GEMM);
    cudaFuncSetAttribute(scores_exp_tc, cudaFuncAttributeMaxDynamicSharedMemorySize, SM_SCR);
    cudaFuncSetAttribute(ctx_attn_tc,   cudaFuncAttributeMaxDynamicSharedMemorySize, SM_CTX);

    dim3 gw(DM * DM / 4 / 256, 4);
    tf_round_w<<<gw, 256>>>(Wq, Wk, Wv, Wo, wp);

    dim3 gq(DM / 128, MTOT / 128, 3);
    gemm_qkv<<<gq, 256, SM_GEMM>>>(Q, K, V, wp, bq, bk, bv, qp, kp, vp);

    dim3 g2(S_ / 128, 1, B_ * H_);
    scores_exp_tc<<<g2, 256, SM_SCR>>>(qp, kp, mask, ep, ip);

    dim3 g3(S_ / 64, 1, B_ * H_);
    ctx_attn_tc<<<g3, 256, SM_CTX>>>(ep, attn, vp, ip, cp);

    dim3 g1(DM / 128, MTOT / 128);
    gemm_out<<<g1, 256, SM_GEMM>>>(cp, wp + 3 * (long)DM * DM, bo, out);
}

// round 15
// speedup vs baseline: 1.1432x; 1.0818x over previous
#include <cuda_runtime.h>
#include <cuda_bf16.h>
#include <cuda_fp16.h>

// Problem constants
#define B_    2
#define H_    16
#define S_    2048
#define D_    64
#define DM    1024
#define MTOT  4096   // B_*S_

static const long OUT_ELEMS  = (long)MTOT * DM;            // 4,194,304
static const long ATTN_ELEMS = (long)B_ * H_ * S_ * S_;    // 134,217,728

// Scratch (device-global; no runtime allocation allowed)
__device__ __half g_q[B_*H_*S_*D_];
__device__ __half g_k[B_*H_*S_*D_];
__device__ __half g_v[B_*H_*S_*D_];
__device__ float  g_ctx[MTOT*DM];
__device__ float  g_attn[(size_t)B_*H_*S_*S_];
__device__ __half g_eraw[(size_t)B_*H_*S_*S_];   // raw e = exp(score+mask), fp16
__device__ float  g_inv[B_*H_*S_];               // per-row 1/sum(exp)
__device__ float  g_w[4*DM*DM];                  // tf32-rounded Wq|Wk|Wv|Wo

// ---------------------------------------------------------------------------
// helpers
// ---------------------------------------------------------------------------
__device__ __forceinline__ float tf(float f) {
    unsigned u;
    asm("cvt.rna.tf32.f32 %0, %1;" : "=r"(u) : "f"(f));
    return __uint_as_float(u);
}
__device__ __forceinline__ float4 tf4(float4 v) {
    float4 t; t.x = tf(v.x); t.y = tf(v.y); t.z = tf(v.z); t.w = tf(v.w); return t;
}

__device__ __forceinline__ void mma_tf32(
    float& c0, float& c1, float& c2, float& c3,
    unsigned a0, unsigned a1, unsigned a2, unsigned a3,
    unsigned b0, unsigned b1)
{
    asm volatile(
        "mma.sync.aligned.m16n8k8.row.col.f32.tf32.tf32.f32 "
        "{%0,%1,%2,%3},{%4,%5,%6,%7},{%8,%9},{%0,%1,%2,%3};"
        : "+f"(c0), "+f"(c1), "+f"(c2), "+f"(c3)
        : "r"(a0), "r"(a1), "r"(a2), "r"(a3), "r"(b0), "r"(b1));
}

// fp16 mma m16n8k16, fp32 accumulate
__device__ __forceinline__ void mma_f16(
    float& c0, float& c1, float& c2, float& c3,
    unsigned a0, unsigned a1, unsigned a2, unsigned a3,
    unsigned b0, unsigned b1)
{
    asm volatile(
        "mma.sync.aligned.m16n8k16.row.col.f32.f16.f16.f32 "
        "{%0,%1,%2,%3},{%4,%5,%6,%7},{%8,%9},{%0,%1,%2,%3};"
        : "+f"(c0), "+f"(c1), "+f"(c2), "+f"(c3)
        : "r"(a0), "r"(a1), "r"(a2), "r"(a3), "r"(b0), "r"(b1));
}

__device__ __forceinline__ void ldsm4(unsigned& r0, unsigned& r1,
                                      unsigned& r2, unsigned& r3,
                                      const float* p)
{
    unsigned a = (unsigned)__cvta_generic_to_shared(p);
    asm volatile("ldmatrix.sync.aligned.m8n8.x4.shared.b16 {%0,%1,%2,%3}, [%4];"
                 : "=r"(r0), "=r"(r1), "=r"(r2), "=r"(r3) : "r"(a));
}
__device__ __forceinline__ void ldsm4h(unsigned& r0, unsigned& r1,
                                       unsigned& r2, unsigned& r3,
                                       const __half* p)
{
    unsigned a = (unsigned)__cvta_generic_to_shared(p);
    asm volatile("ldmatrix.sync.aligned.m8n8.x4.shared.b16 {%0,%1,%2,%3}, [%4];"
                 : "=r"(r0), "=r"(r1), "=r"(r2), "=r"(r3) : "r"(a));
}
__device__ __forceinline__ void ldsm4ht(unsigned& r0, unsigned& r1,
                                        unsigned& r2, unsigned& r3,
                                        const __half* p)
{
    unsigned a = (unsigned)__cvta_generic_to_shared(p);
    asm volatile("ldmatrix.sync.aligned.m8n8.x4.trans.shared.b16 {%0,%1,%2,%3}, [%4];"
                 : "=r"(r0), "=r"(r1), "=r"(r2), "=r"(r3) : "r"(a));
}

// 16B async copy gmem -> smem
__device__ __forceinline__ void cpa16(void* dst, const void* src) {
    unsigned d = (unsigned)__cvta_generic_to_shared(dst);
    asm volatile("cp.async.cg.shared.global [%0], [%1], 16;" :: "r"(d), "l"(src));
}
#define CPA_COMMIT asm volatile("cp.async.commit_group;")
#define CPA_WAIT0  asm volatile("cp.async.wait_group 0;")
#define CPA_WAIT1  asm volatile("cp.async.wait_group 1;")

__device__ __forceinline__ unsigned pkh2(float a, float b) {
    __half2 h = __floats2half2_rn(a, b);
    return *reinterpret_cast<unsigned*>(&h);
}

// Row-major padded strides
#define ASTR  36    // gemm A tile rows (32 k floats + pad)
#define QSTRH 72    // fp16 rows: 64 halves + 8 pad (144B; stride%128B=16 -> LDSM clean)
// gemm W layout (kk-interleaved, scalar LDS)
#define RSB 132
#define CSB 1056

// ---------------------------------------------------------------------------
// Prep: round all four weight matrices to tf32 once.  grid (1024, 4)
// ---------------------------------------------------------------------------
__global__ __launch_bounds__(256)
void tf_round_w(const float* __restrict__ Wq, const float* __restrict__ Wk,
                const float* __restrict__ Wv, const float* __restrict__ Wo,
                float* __restrict__ dst)
{
    const float* src = (blockIdx.y == 0) ? Wq : (blockIdx.y == 1) ? Wk
                     : (blockIdx.y == 2) ? Wv : Wo;
    long i = (long)blockIdx.x * 256 + threadIdx.x;
    float* d = dst + (long)blockIdx.y * DM * DM;
    ((float4*)d)[i] = tf4(((const float4*)src)[i]);
}

// ---------------------------------------------------------------------------
// Dense GEMM body: 3-stage cp.async ring, wait_group 1. (R12 winner.)
// SPLIT=1 scatters fp16 output to [B,H,S,D].
// ---------------------------------------------------------------------------
template<int SPLIT, int PREA>
__device__ __forceinline__
void gemm_body(const float* __restrict__ A, const float* __restrict__ W,
               const float* __restrict__ bias, float* __restrict__ C,
               float* sm, int bx, int by)
{
    float* As = sm;            // 3 bufs * 128*ASTR = 13824
    float* Bs = sm + 13824;    // 3 bufs * 4*CSB = 12672

    const int tid = threadIdx.x, lane = tid & 31, warp = tid >> 5;
    const int wm = warp >> 2, wn = warp & 3;
    const float* Ab = A + (long)by * 128 * DM;
    const float* Wb = W + (long)bx * 128;

    const int a_ch = tid & 3, a_m = tid >> 2;
    const int b_cg = tid & 31, b_k = tid >> 5;
    const int b_kk = 2 * (b_k & 3) + ((b_k >> 2) & 1);

    const int arow = lane & 15;
    const int acol = ((lane >> 4) & 1) * 4;

    float acc[4][4][4];
    #pragma unroll
    for (int i = 0; i < 4; i++)
        #pragma unroll
        for (int j = 0; j < 4; j++)
            #pragma unroll
            for (int q = 0; q < 4; q++) acc[i][j][q] = 0.f;

    float4 ar[2][2];
    const int NK = DM / 32;

    #pragma unroll
    for (int t = 0; t < 2; t++) {
        float* Bd = Bs + t * 4224;
        #pragma unroll
        for (int p = 0; p < 4; p++)
            cpa16(Bd + p * CSB + b_kk * RSB + b_cg * 4,
                  Wb + (long)(t * 32 + b_k + 8 * p) * DM + b_cg * 4);
        float* Ad = As + t * 4608;
        if (PREA) {
            #pragma unroll
            for (int p = 0; p < 2; p++) {
                const float* s = Ab + (long)(a_m + 64 * p) * DM + t * 32 + a_ch * 8;
                float* d = Ad + (a_m + 64 * p) * ASTR + a_ch * 8;
                cpa16(d, s);
                cpa16(d + 4, s + 4);
            }
        } else {
            #pragma unroll
            for (int p = 0; p < 2; p++) {
                const float* s = Ab + (long)(a_m + 64 * p) * DM + t * 32 + a_ch * 8;
                ar[p][0] = *(const float4*)s;
                ar[p][1] = *(const float4*)(s + 4);
            }
            #pragma unroll
            for (int p = 0; p < 2; p++) {
                float* d = Ad + (a_m + 64 * p) * ASTR + a_ch * 8;
                *(float4*)d = tf4(ar[p][0]);
                *(float4*)(d + 4) = tf4(ar[p][1]);
            }
        }
        CPA_COMMIT;
    }
    CPA_WAIT1;
    __syncthreads();

    for (int it = 0; it < NK; ++it) {
        const bool pre2 = (it + 2 < NK);
        if (!PREA && pre2) {
            const int k0 = (it + 2) * 32;
            #pragma unroll
            for (int p = 0; p < 2; p++) {
                const float* s = Ab + (long)(a_m + 64 * p) * DM + k0 + a_ch * 8;
                ar[p][0] = *(const float4*)s;
                ar[p][1] = *(const float4*)(s + 4);
            }
        }

        const int ib = it % 3;
        const float* Ac = As + ib * 4608;
        const float* Bc = Bs + ib * 4224;
        #pragma unroll
        for (int ch = 0; ch < 4; ch++) {
            unsigned a[4][4], b[4][2];
            #pragma unroll
            for (int mi = 0; mi < 4; mi++)
                ldsm4(a[mi][0], a[mi][1], a[mi][2], a[mi][3],
                      Ac + (wm * 64 + mi * 16 + arow) * ASTR + ch * 8 + acol);
            #pragma unroll
            for (int ni = 0; ni < 4; ni++) {
                int n = wn * 32 + ni * 8 + (lane >> 2);
                int c2 = 2 * (lane & 3);
                b[ni][0] = __float_as_uint(Bc[ch * CSB + c2 * RSB + n]);
                b[ni][1] = __float_as_uint(Bc[ch * CSB + (c2 + 1) * RSB + n]);
            }
            #pragma unroll
            for (int mi = 0; mi < 4; mi++)
                #pragma unroll
                for (int ni = 0; ni < 4; ni++)
                    mma_tf32(acc[mi][ni][0], acc[mi][ni][1], acc[mi][ni][2], acc[mi][ni][3],
                             a[mi][0], a[mi][1], a[mi][2], a[mi][3],
                             b[ni][0], b[ni][1]);
        }

        if (pre2) {
            const int k0 = (it + 2) * 32;
            const int nb = (it + 2) % 3;
            float* Bd = Bs + nb * 4224;
            #pragma unroll
            for (int p = 0; p < 4; p++)
                cpa16(Bd + p * CSB + b_kk * RSB + b_cg * 4,
                      Wb + (long)(k0 + b_k + 8 * p) * DM + b_cg * 4);
            float* Ad = As + nb * 4608;
            if (PREA) {
                #pragma unroll
                for (int p = 0; p < 2; p++) {
                    const float* s = Ab + (long)(a_m + 64 * p) * DM + k0 + a_ch * 8;
                    float* d = Ad + (a_m + 64 * p) * ASTR + a_ch * 8;
                    cpa16(d, s);
                    cpa16(d + 4, s + 4);
                }
            } else {
                #pragma unroll
                for (int p = 0; p < 2; p++) {
                    float* d = Ad + (a_m + 64 * p) * ASTR + a_ch * 8;
                    *(float4*)d = tf4(ar[p][0]);
                    *(float4*)(d + 4) = tf4(ar[p][1]);
                }
            }
        }
        CPA_COMMIT;

        if (it + 1 < NK) {
            CPA_WAIT1;
            __syncthreads();
        }
    }

    #pragma unroll
    for (int mi = 0; mi < 4; mi++) {
        int r0 = by * 128 + wm * 64 + mi * 16 + (lane >> 2);
        #pragma unroll
        for (int ni = 0; ni < 4; ni++) {
            int n = bx * 128 + wn * 32 + ni * 8 + 2 * (lane & 3);
            float bz0 = bias[n], bz1 = bias[n + 1];
            if (SPLIT) {
                // fp16 q/k/v for the attention kernels
                __half* Ch = (__half*)C;
                int bb = r0 >> 11, s = r0 & 2047;
                int h = n >> 6, d = n & 63;
                long base = (((long)(bb * H_ + h)) * S_ + s) * D_ + d;
                *(unsigned*)(Ch + base) = pkh2(acc[mi][ni][0] + bz0, acc[mi][ni][1] + bz1);
                *(unsigned*)(Ch + base + 8 * D_) = pkh2(acc[mi][ni][2] + bz0, acc[mi][ni][3] + bz1);
            } else {
                float2 t0, t1;
                t0.x = acc[mi][ni][0] + bz0; t0.y = acc[mi][ni][1] + bz1;
                t1.x = acc[mi][ni][2] + bz0; t1.y = acc[mi][ni][3] + bz1;
                *(float2*)(C + (long)r0 * DM + n) = t0;
                *(float2*)(C + (long)(r0 + 8) * DM + n) = t1;
            }
        }
    }
}

__global__ __launch_bounds__(256)
void gemm_qkv(const float* __restrict__ Q, const float* __restrict__ K,
              const float* __restrict__ V, const float* __restrict__ Wt,
              const float* __restrict__ bq, const float* __restrict__ bk,
              const float* __restrict__ bv,
              __half* __restrict__ qo, __half* __restrict__ ko, __half* __restrict__ vo)
{
    extern __shared__ float sm[];
    const int z = blockIdx.z;
    const float* A    = (z == 0) ? Q  : (z == 1) ? K  : V;
    const float* W    = Wt + (long)z * DM * DM;
    const float* bias = (z == 0) ? bq : (z == 1) ? bk : bv;
    __half* C         = (z == 0) ? qo : (z == 1) ? ko : vo;
    gemm_body<1, 0>(A, W, bias, (float*)C, sm, blockIdx.x, blockIdx.y);
}

__global__ __launch_bounds__(256)
void gemm_out(const float* __restrict__ A, const float* __restrict__ W,
              const float* __restrict__ bias, float* __restrict__ C)
{
    extern __shared__ float sm[];
    gemm_body<0, 1>(A, W, bias, C, sm, blockIdx.x, blockIdx.y);
}

// ---------------------------------------------------------------------------
// K2: scores -> raw e (fp16) + row sums. fp16 MMA m16n8k16.
// 128-row CTA, 8 warps 4m x 2n (warp 32 rows x 32 of 64 keys), 2 CTAs/SM.
// Smem: msk 2048f | red 256f | Qs 128*72h | Ks 2*64*72h  = 46080 B
// ---------------------------------------------------------------------------
__global__ __launch_bounds__(256, 2)
void scores_exp_tc(const __half* __restrict__ Qh, const __half* __restrict__ Kh,
                   const float* __restrict__ mask,
                   __half* __restrict__ eraw, float* __restrict__ inv_out)
{
    extern __shared__ float sm[];
    float*  msk = sm;                       // 2048
    float*  red = sm + 2048;                // 256
    __half* Qs  = (__half*)(sm + 2304);     // 128*QSTRH = 9216 halves
    __half* Ks  = Qs + 9216;                // 2 bufs * 64*QSTRH = 9216 halves

    const int tid = threadIdx.x, lane = tid & 31, warp = tid >> 5;
    const int wm = warp >> 1, wn = warp & 1;
    const int bh = blockIdx.z;
    const int row0 = blockIdx.x * 128;
    const __half* Qb = Qh + ((long)bh * S_ + row0) * D_;
    const __half* Kb = Kh + (long)bh * S_ * D_;
    __half* eb = eraw + (long)bh * S_ * S_ + (long)row0 * S_;
    const int bb = bh >> 4;

    #pragma unroll
    for (int i = tid; i < 512; i += 256)
        ((float4*)msk)[i] = ((const float4*)(mask + (long)bb * S_))[i];

    const int ch = tid & 7, m = tid >> 3;   // ch: 16B segment (8 halves), m: row

    // Q (128 rows) + K tile 0 (64 keys) via cp.async (one 16B per row-segment)
    #pragma unroll
    for (int p = 0; p < 4; p++) {
        int row = m + 32 * p;
        cpa16(Qs + row * QSTRH + ch * 8, Qb + (long)row * D_ + ch * 8);
    }
    #pragma unroll
    for (int p = 0; p < 2; p++) {
        int row = m + 32 * p;
        cpa16(Ks + row * QSTRH + ch * 8, Kb + (long)row * D_ + ch * 8);
    }
    CPA_COMMIT;
    CPA_WAIT0;
    __syncthreads();

    // LDSM addressing (halves)
    const int arow = lane & 15;                    // A: rows 0..15 of 16-row tile
    const int acol = ((lane >> 4) & 1) * 8;        // A: k 0/8
    const int bro  = (lane & 7) + ((lane >> 4) & 1) * 8;   // B: n row within 16
    const int bco  = ((lane >> 3) & 1) * 8;                // B: k 0/8

    const int r_w = wm * 32 + (lane >> 2);
    float ssum[4] = {0.f, 0.f, 0.f, 0.f};

    const int NT = S_ / 64;   // 32
    for (int kt = 0; kt < NT; ++kt) {
        const bool pre = (kt + 1 < NT);
        if (pre) {
            const int k0 = (kt + 1) * 64;
            __half* Kd = Ks + ((kt + 1) & 1) * 4608;
            #pragma unroll
            for (int p = 0; p < 2; p++) {
                int row = m + 32 * p;
                cpa16(Kd + row * QSTRH + ch * 8, Kb + (long)(k0 + row) * D_ + ch * 8);
            }
            CPA_COMMIT;
        }

        float acc[2][4][4];
        #pragma unroll
        for (int i = 0; i < 2; i++)
            #pragma unroll
            for (int j = 0; j < 4; j++)
                #pragma unroll
                for (int q = 0; q < 4; q++) acc[i][j][q] = 0.f;

        const __half* Kc = Ks + (kt & 1) * 4608;
        #pragma unroll
        for (int c = 0; c < 4; c++) {     // 4 chunks of k16 over D=64
            unsigned a[2][4], b[4][2];
            #pragma unroll
            for (int mi = 0; mi < 2; mi++)
                ldsm4h(a[mi][0], a[mi][1], a[mi][2], a[mi][3],
                       Qs + (wm * 32 + mi * 16 + arow) * QSTRH + c * 16 + acol);
            #pragma unroll
            for (int pr = 0; pr < 2; pr++)
                ldsm4h(b[2*pr][0], b[2*pr][1], b[2*pr+1][0], b[2*pr+1][1],
                       Kc + (wn * 32 + pr * 16 + bro) * QSTRH + c * 16 + bco);
            #pragma unroll
            for (int mi = 0; mi < 2; mi++)
                #pragma unroll
                for (int ni = 0; ni < 4; ni++)
                    mma_f16(acc[mi][ni][0], acc[mi][ni][1], acc[mi][ni][2], acc[mi][ni][3],
                            a[mi][0], a[mi][1], a[mi][2], a[mi][3],
                            b[ni][0], b[ni][1]);
        }

        #pragma unroll
        for (int mi = 0; mi < 2; mi++) {
            int r = r_w + mi * 16;
            #pragma unroll
            for (int ni = 0; ni < 4; ni++) {
                int n = kt * 64 + wn * 32 + ni * 8 + 2 * (lane & 3);
                float2 mm = *(const float2*)(msk + n);
                float e0 = __expf(fmaf(acc[mi][ni][0], 0.125f, -1e9f * mm.x));
                float e1 = __expf(fmaf(acc[mi][ni][1], 0.125f, -1e9f * mm.y));
                float e2 = __expf(fmaf(acc[mi][ni][2], 0.125f, -1e9f * mm.x));
                float e3 = __expf(fmaf(acc[mi][ni][3], 0.125f, -1e9f * mm.y));
                __stcs((unsigned*)(eb + (long)r * S_ + n), pkh2(e0, e1));
                __stcs((unsigned*)(eb + (long)(r + 8) * S_ + n), pkh2(e2, e3));
                ssum[mi*2]   += e0 + e1;
                ssum[mi*2+1] += e2 + e3;
            }
        }

        if (pre) {
            CPA_WAIT0;
            __syncthreads();
        }
    }

    #pragma unroll
    for (int i = 0; i < 4; i++) {
        ssum[i] += __shfl_xor_sync(0xFFFFFFFFu, ssum[i], 1);
        ssum[i] += __shfl_xor_sync(0xFFFFFFFFu, ssum[i], 2);
    }
    if ((lane & 3) == 0) {
        #pragma unroll
        for (int mi = 0; mi < 2; mi++)
            #pragma unroll
            for (int h = 0; h < 2; h++)
                red[wn * 128 + r_w + mi * 16 + 8 * h] = ssum[mi * 2 + h];
    }
    __syncthreads();
    if (tid < 128)
        inv_out[(long)bh * S_ + row0 + tid] = 1.0f / (red[tid] + red[128 + tid]);
}

// ---------------------------------------------------------------------------
// K3: read fp16 raw e, normalize -> fp32 attn write + P@V (fp16 MMA).
// 64-row CTAs, 3 CTAs/SM. P staged fp16; V via ldmatrix.trans.
// Smem: invs 64f | Ps 2*64*72h | Vs 2*64*72h = 37120 B
// ---------------------------------------------------------------------------
__global__ __launch_bounds__(256, 3)
void ctx_attn_tc(const __half* __restrict__ eraw, float* __restrict__ attn,
                 const __half* __restrict__ Vh, const float* __restrict__ inv_in,
                 float* __restrict__ ctx)
{
    extern __shared__ float sm[];
    float*  invs = sm;                      // 64
    __half* Ps   = (__half*)(sm + 64);      // 2 bufs * 64*QSTRH = 9216 halves
    __half* Vs   = Ps + 9216;               // 2 bufs * 64*QSTRH = 9216 halves

    const int tid = threadIdx.x, lane = tid & 31, warp = tid >> 5;
    const int wm = warp >> 1, wn = warp & 1;
    const int bh = blockIdx.z;
    const int row0 = blockIdx.x * 64;
    const __half* rawb = eraw + (long)bh * S_ * S_ + (long)row0 * S_;
    float* attnb = attn + (long)bh * S_ * S_ + (long)row0 * S_;
    const __half* Vb = Vh + (long)bh * S_ * D_;

    if (tid < 64) invs[tid] = inv_in[(long)bh * S_ + row0 + tid];
    __syncthreads();

    const int c16 = tid & 15, rl = tid >> 4;   // e loader: 16 rows x 16 col-groups of 4
    const int ch = tid & 7, m = tid >> 3;      // V loader

    // LDSM addressing (halves)
    const int arow = lane & 15;
    const int acol = ((lane >> 4) & 1) * 8;
    const int vrow = (lane & 7) + ((lane >> 3) & 1) * 8;   // V trans: k row within 16
    const int vcol = ((lane >> 4) & 1) * 8;                // V trans: d 0/8

    uint2 hr[4];

    // prologue: V tile 0 via cp.async; e tile 0 via registers
    #pragma unroll
    for (int p = 0; p < 2; p++) {
        int key = m + 32 * p;
        cpa16(Vs + key * QSTRH + ch * 8, Vb + (long)key * D_ + ch * 8);
    }
    CPA_COMMIT;
    #pragma unroll
    for (int p = 0; p < 4; p++)
        hr[p] = __ldcs((const uint2*)(rawb + (long)(rl + 16 * p) * S_ + c16 * 4));

    {
        #pragma unroll
        for (int p = 0; p < 4; p++) {
            int row = rl + 16 * p;
            float iv = invs[row];
            float2 f01 = __half22float2(*reinterpret_cast<__half2*>(&hr[p].x));
            float2 f23 = __half22float2(*reinterpret_cast<__half2*>(&hr[p].y));
            float4 e;
            e.x = f01.x * iv; e.y = f01.y * iv;
            e.z = f23.x * iv; e.w = f23.y * iv;
            __stcs((float4*)(attnb + (long)row * S_ + c16 * 4), e);
            uint2 hp;
            hp.x = pkh2(e.x, e.y);
            hp.y = pkh2(e.z, e.w);
            *(uint2*)(Ps + row * QSTRH + c16 * 4) = hp;
        }
    }
    CPA_WAIT0;
    __syncthreads();

    float acc[4][4];
    #pragma unroll
    for (int j = 0; j < 4; j++)
        #pragma unroll
        for (int q = 0; q < 4; q++) acc[j][q] = 0.f;

    const int NT = S_ / 64;   // 32
    for (int kt = 0; kt < NT; ++kt) {
        const bool pre = (kt + 1 < NT);
        if (pre) {
            const int k0 = (kt + 1) * 64;
            __half* Vd = Vs + ((kt + 1) & 1) * 4608;
            #pragma unroll
            for (int p = 0; p < 2; p++) {
                int key = m + 32 * p;
                cpa16(Vd + key * QSTRH + ch * 8, Vb + (long)(k0 + key) * D_ + ch * 8);
            }
            CPA_COMMIT;
            #pragma unroll
            for (int p = 0; p < 4; p++)
                hr[p] = __ldcs((const uint2*)(rawb + (long)(rl + 16 * p) * S_ + k0 + c16 * 4));
        }

        const __half* Pc = Ps + (kt & 1) * 4608;
        const __half* Vc = Vs + (kt & 1) * 4608;
        #pragma unroll
        for (int c = 0; c < 4; c++) {     // 4 chunks of key16 over 64-key tile
            unsigned a[4], b[4][2];
            ldsm4h(a[0], a[1], a[2], a[3],
                   Pc + (wm * 16 + arow) * QSTRH + c * 16 + acol);
            #pragma unroll
            for (int t = 0; t < 2; t++)    // d tiles of 16 within warp's 32 d
                ldsm4ht(b[2*t][0], b[2*t][1], b[2*t+1][0], b[2*t+1][1],
                        Vc + (c * 16 + vrow) * QSTRH + wn * 32 + t * 16 + vcol);
            #pragma unroll
            for (int ni = 0; ni < 4; ni++)
                mma_f16(acc[ni][0], acc[ni][1], acc[ni][2], acc[ni][3],
                        a[0], a[1], a[2], a[3], b[ni][0], b[ni][1]);
        }

        if (pre) {
            const int k0 = (kt + 1) * 64;
            __half* Pd = Ps + ((kt + 1) & 1) * 4608;
            #pragma unroll
            for (int p = 0; p < 4; p++) {
                int row = rl + 16 * p;
                float iv = invs[row];
                float2 f01 = __half22float2(*reinterpret_cast<__half2*>(&hr[p].x));
                float2 f23 = __half22float2(*reinterpret_cast<__half2*>(&hr[p].y));
                float4 e;
                e.x = f01.x * iv; e.y = f01.y * iv;
                e.z = f23.x * iv; e.w = f23.y * iv;
                __stcs((float4*)(attnb + (long)row * S_ + k0 + c16 * 4), e);
                uint2 hp;
                hp.x = pkh2(e.x, e.y);
                hp.y = pkh2(e.z, e.w);
                *(uint2*)(Pd + row * QSTRH + c16 * 4) = hp;
            }
            CPA_WAIT0;
            __syncthreads();
        }
    }

    const int bb = bh >> 4, h = bh & 15;
    {
        int s = row0 + wm * 16 + (lane >> 2);
        #pragma unroll
        for (int ni = 0; ni < 4; ni++) {
            int d = wn * 32 + ni * 8 + 2 * (lane & 3);
            long base = ((long)bb * S_ + s) * DM + h * 64 + d;
            float2 t0, t1;
            t0.x = tf(acc[ni][0]); t0.y = tf(acc[ni][1]);
            t1.x = tf(acc[ni][2]); t1.y = tf(acc[ni][3]);
            *(float2*)(ctx + base) = t0;
            *(float2*)(ctx + base + 8 * DM) = t1;
        }
    }
}

// ---------------------------------------------------------------------------
extern "C" void kernel_launch(void* const* d_in, const int* in_sizes, int n_in,
                              void* d_out, int out_size) {
    const float* Q    = (const float*)d_in[0];
    const float* K    = (const float*)d_in[1];
    const float* V    = (const float*)d_in[2];
    const float* mask = (const float*)d_in[3];
    const float* Wq   = (const float*)d_in[4];
    const float* bq   = (const float*)d_in[5];
    const float* Wk   = (const float*)d_in[6];
    const float* bk   = (const float*)d_in[7];
    const float* Wv   = (const float*)d_in[8];
    const float* bv   = (const float*)d_in[9];
    const float* Wo   = (const float*)d_in[10];
    const float* bo   = (const float*)d_in[11];
    float* out = (float*)d_out;

    float *cp, *ap, *ip, *wp;
    __half *qp, *kp, *vp, *ep;
    cudaGetSymbolAddress((void**)&qp, g_q);
    cudaGetSymbolAddress((void**)&kp, g_k);
    cudaGetSymbolAddress((void**)&vp, g_v);
    cudaGetSymbolAddress((void**)&cp, g_ctx);
    cudaGetSymbolAddress((void**)&ap, g_attn);
    cudaGetSymbolAddress((void**)&ep, g_eraw);
    cudaGetSymbolAddress((void**)&ip, g_inv);
    cudaGetSymbolAddress((void**)&wp, g_w);

    float* attn = ((long)out_size >= OUT_ELEMS + ATTN_ELEMS) ? (out + OUT_ELEMS) : ap;

    const int SM_GEMM = (13824 + 12672) * 4;     // 105984
    const int SM_SCR  = 2304 * 4 + 18432 * 2;    // 46080
    const int SM_CTX  = 64 * 4 + 18432 * 2;      // 37120
    cudaFuncSetAttribute(gemm_qkv, cudaFuncAttributeMaxDynamicSharedMemorySize, SM_GEMM);
    cudaFuncSetAttribute(gemm_out, cudaFuncAttributeMaxDynamicSharedMemorySize, SM_GEMM);
    cudaFuncSetAttribute(scores_exp_tc, cudaFuncAttributeMaxDynamicSharedMemorySize, SM_SCR);
    cudaFuncSetAttribute(ctx_attn_tc,   cudaFuncAttributeMaxDynamicSharedMemorySize, SM_CTX);

    dim3 gw(DM * DM / 4 / 256, 4);
    tf_round_w<<<gw, 256>>>(Wq, Wk, Wv, Wo, wp);

    dim3 gq(DM / 128, MTOT / 128, 3);
    gemm_qkv<<<gq, 256, SM_GEMM>>>(Q, K, V, wp, bq, bk, bv, qp, kp, vp);

    dim3 g2(S_ / 128, 1, B_ * H_);
    scores_exp_tc<<<g2, 256, SM_SCR>>>(qp, kp, mask, ep, ip);

    dim3 g3(S_ / 64, 1, B_ * H_);
    ctx_attn_tc<<<g3, 256, SM_CTX>>>(ep, attn, vp, ip, cp);

    dim3 g1(DM / 128, MTOT / 128);
    gemm_out<<<g1, 256, SM_GEMM>>>(cp, wp + 3 * (long)DM * DM, bo, out);
}